// round 16
// baseline (speedup 1.0000x reference)
#include <cuda_runtime.h>
#include <cstdint>

#define D_IN   768
#define D_SAE  12288
#define T_LEN  64
#define KTOP   64
#define BATCH  32
#define NROWS  (BATCH * T_LEN)   // 2048

// ---------------- scratch (static device globals; no allocations) ----------------
__device__ __align__(16) float g_pre[(size_t)NROWS * D_SAE];     // 96 MB (exact fp32)
__device__ float g_gate[D_SAE];
__device__ int   g_topidx[NROWS * 128];   // SORTED by composite desc
__device__ float g_topval[NROWS * 128];
__device__ int   g_zidx[NROWS * KTOP];
__device__ float g_zval[NROWS * KTOP];
__device__ float g_rowloss[NROWS];
__device__ unsigned int g_done;           // decode completion counter (reset by last CTA)

// ---------------- helpers ----------------
__device__ __forceinline__ unsigned long long pack2(float x, float y) {
    unsigned long long r;
    asm("mov.b64 %0, {%1, %2};" : "=l"(r) : "f"(x), "f"(y));
    return r;
}
__device__ __forceinline__ float2 unpack2(unsigned long long v) {
    float2 f;
    asm("mov.b64 {%0, %1}, %2;" : "=f"(f.x), "=f"(f.y) : "l"(v));
    return f;
}
__device__ __forceinline__ void fma2(unsigned long long& c, unsigned long long a, unsigned long long b) {
    asm("fma.rn.f32x2 %0, %1, %2, %0;" : "+l"(c) : "l"(a), "l"(b));
}
__device__ __forceinline__ unsigned int fkey(float v) {
    unsigned int u = __float_as_uint(v);
    return (u & 0x80000000u) ? ~u : (u | 0x80000000u);
}
__device__ __forceinline__ float keyToFloat(unsigned int k) {
    unsigned int u = (k & 0x80000000u) ? (k & 0x7FFFFFFFu) : ~k;
    return __uint_as_float(u);
}
// larger == (greater value) or (equal value, smaller index)  [jax top_k tie rule]
__device__ __forceinline__ unsigned long long makeComp(float v, int idx) {
    return ((unsigned long long)fkey(v) << 32) | (unsigned long long)(0xFFFFFFFFu - (unsigned int)idx);
}

// ======================================================================
// Kernel A: fp32 GEMM, 128x64 tile, 2 CTAs/SM (tail-quantization fix).
// Per thread: 8 m-rows (4 f32x2 pairs) x 4 n. Same FFMA2 inner scheme.
// ======================================================================
__global__ __launch_bounds__(256, 2) void gemm_enc(const float* __restrict__ X,
                                                   const float* __restrict__ W,
                                                   const float* __restrict__ bias) {
    __shared__ __align__(16) float As[2][16][128];   // 16 KB  [k][m]
    __shared__ __align__(16) float Bs[2][16][64];    //  8 KB  [k][n]

    const int tid  = threadIdx.x;
    const int row0 = blockIdx.y * 128;
    const int col0 = blockIdx.x * 64;
    const int tx = tid & 15, ty = tid >> 4;          // n-group, m-group

    const int aRow = tid >> 2;           // 0..63
    const int aCol = (tid & 3) * 4;      // 0,4,8,12
    const int bRow = tid >> 4;           // 0..15
    const int bCol = (tid & 15) * 4;     // 0..60

    const float* Aptr = X + (size_t)row0 * D_IN;
    const float* Bptr = W + col0;

    float4 a0, a1, b0;
    a0 = *(const float4*)(Aptr + (size_t)aRow * D_IN + aCol);
    a1 = *(const float4*)(Aptr + (size_t)(aRow + 64) * D_IN + aCol);
    b0 = *(const float4*)(Bptr + (size_t)bRow * D_SAE + bCol);
    As[0][aCol + 0][aRow] = a0.x; As[0][aCol + 1][aRow] = a0.y;
    As[0][aCol + 2][aRow] = a0.z; As[0][aCol + 3][aRow] = a0.w;
    As[0][aCol + 0][aRow + 64] = a1.x; As[0][aCol + 1][aRow + 64] = a1.y;
    As[0][aCol + 2][aRow + 64] = a1.z; As[0][aCol + 3][aRow + 64] = a1.w;
    *(float4*)&Bs[0][bRow][bCol] = b0;
    __syncthreads();

    unsigned long long cc[4][4];
#pragma unroll
    for (int i = 0; i < 4; ++i)
#pragma unroll
        for (int j = 0; j < 4; ++j) cc[i][j] = 0ull;

    const int NKT = D_IN / 16;  // 48
    for (int kt = 0; kt < NKT; ++kt) {
        const int cur = kt & 1;
        if (kt < NKT - 1) {
            const int k0 = (kt + 1) * 16;
            a0 = *(const float4*)(Aptr + (size_t)aRow * D_IN + k0 + aCol);
            a1 = *(const float4*)(Aptr + (size_t)(aRow + 64) * D_IN + k0 + aCol);
            b0 = *(const float4*)(Bptr + (size_t)(k0 + bRow) * D_SAE + bCol);
        }
#pragma unroll
        for (int k = 0; k < 16; ++k) {
            ulonglong2 aa01 = *(const ulonglong2*)&As[cur][k][ty * 8];
            ulonglong2 aa23 = *(const ulonglong2*)&As[cur][k][ty * 8 + 4];
            float4 bv = *(const float4*)&Bs[cur][k][tx * 4];
            unsigned long long av[4] = {aa01.x, aa01.y, aa23.x, aa23.y};
            unsigned long long bb[4] = {pack2(bv.x, bv.x), pack2(bv.y, bv.y),
                                        pack2(bv.z, bv.z), pack2(bv.w, bv.w)};
#pragma unroll
            for (int i = 0; i < 4; ++i)
#pragma unroll
                for (int j = 0; j < 4; ++j) fma2(cc[i][j], av[i], bb[j]);
        }
        if (kt < NKT - 1) {
            const int nxt = cur ^ 1;
            As[nxt][aCol + 0][aRow] = a0.x; As[nxt][aCol + 1][aRow] = a0.y;
            As[nxt][aCol + 2][aRow] = a0.z; As[nxt][aCol + 3][aRow] = a0.w;
            As[nxt][aCol + 0][aRow + 64] = a1.x; As[nxt][aCol + 1][aRow + 64] = a1.y;
            As[nxt][aCol + 2][aRow + 64] = a1.z; As[nxt][aCol + 3][aRow + 64] = a1.w;
            *(float4*)&Bs[nxt][bRow][bCol] = b0;
        }
        __syncthreads();
    }

    const float4 bb4 = *(const float4*)(bias + col0 + tx * 4);
#pragma unroll
    for (int p = 0; p < 4; ++p) {
        const float2 v0 = unpack2(cc[p][0]);
        const float2 v1 = unpack2(cc[p][1]);
        const float2 v2 = unpack2(cc[p][2]);
        const float2 v3 = unpack2(cc[p][3]);
        const int m = ty * 8 + p * 2;
        size_t base = (size_t)(row0 + m) * D_SAE + col0 + tx * 4;
        float4 o;
        o.x = v0.x + bb4.x; o.y = v1.x + bb4.y; o.z = v2.x + bb4.z; o.w = v3.x + bb4.w;
        *(float4*)&g_pre[base] = o;
        o.x = v0.y + bb4.x; o.y = v1.y + bb4.y; o.z = v2.y + bb4.z; o.w = v3.y + bb4.w;
        *(float4*)&g_pre[base + D_SAE] = o;
    }
}

// ======================================================================
// Kernel B: exact top-128 per row via threshold-from-maxes (no histogram).
// Blocks 0..47 also fill the gate table (runs before scan launch).
// ======================================================================
#define TK_CAP 4096
__global__ __launch_bounds__(256, 2) void topk128(const float* __restrict__ gate_raw) {
    __shared__ __align__(16) float sMax[256];
    __shared__ __align__(16) unsigned long long cand[TK_CAP + 8];
    __shared__ unsigned int sTkey;
    __shared__ int sCount;

    const int row = blockIdx.x, tid = threadIdx.x, lane = tid & 31;
    const float* rp = g_pre + (size_t)row * D_SAE;

    if (row < D_SAE / 256) {
        const int gi = row * 256 + tid;
        g_gate[gi] = 1.0f / (1.0f + expf(-gate_raw[gi]));
    }

    float v[48];
#pragma unroll
    for (int i = 0; i < 12; ++i) {
        const float4 q = *(const float4*)(rp + (size_t)(tid + i * 256) * 4);
        v[i * 4 + 0] = q.x; v[i * 4 + 1] = q.y; v[i * 4 + 2] = q.z; v[i * 4 + 3] = q.w;
    }
    float m = v[0];
#pragma unroll
    for (int i = 1; i < 48; ++i) m = fmaxf(m, v[i]);
    sMax[tid] = m;
    if (tid == 0) { sTkey = 0xFFFFFFFFu; sCount = 0; }
    __syncthreads();

    {
        const unsigned int mk = fkey(m);
        int r = 0;
#pragma unroll
        for (int j = 0; j < 256; j += 4) {
            const float4 q = *(const float4*)&sMax[j];
            r += (fkey(q.x) > mk) + (fkey(q.y) > mk) + (fkey(q.z) > mk) + (fkey(q.w) > mk);
        }
        if (r <= 127) atomicMin(&sTkey, mk);
    }
    __syncthreads();
    const unsigned int T = sTkey;

#pragma unroll
    for (int i = 0; i < 48; ++i) {
        const int flag = (fkey(v[i]) >= T);
        const unsigned bal = __ballot_sync(0xFFFFFFFFu, flag);
        if (bal) {
            int base = 0;
            if (lane == 0) base = atomicAdd(&sCount, __popc(bal));
            base = __shfl_sync(0xFFFFFFFFu, base, 0);
            if (flag) {
                const int pos = base + __popc(bal & ((1u << lane) - 1));
                if (pos < TK_CAP) {
                    const int idx = (tid + (i >> 2) * 256) * 4 + (i & 3);
                    cand[pos] = makeComp(v[i], idx);
                }
            }
        }
    }
    __syncthreads();

    const int nc = min(sCount, TK_CAP);
    if (tid < 8) cand[nc + tid] = 0ull;
    __syncthreads();

    for (int c = tid; c < nc; c += 256) {
        const unsigned long long me = cand[c];
        int r = 0;
        for (int j = 0; j < nc; j += 8) {
            const ulonglong2 c0 = *(const ulonglong2*)&cand[j];
            const ulonglong2 c1 = *(const ulonglong2*)&cand[j + 2];
            const ulonglong2 c2 = *(const ulonglong2*)&cand[j + 4];
            const ulonglong2 c3 = *(const ulonglong2*)&cand[j + 6];
            r += (c0.x > me) + (c0.y > me) + (c1.x > me) + (c1.y > me)
               + (c2.x > me) + (c2.y > me) + (c3.x > me) + (c3.y > me);
        }
        if (r < 128) {
            g_topidx[row * 128 + r] = (int)(0xFFFFFFFFu - (unsigned int)me);
            g_topval[row * 128 + r] = keyToFloat((unsigned int)(me >> 32));
        }
    }
}

// ======================================================================
// Kernel C: scan (R14 measured-best; frozen).
// ======================================================================
__global__ __launch_bounds__(128) void scan_kernel(float* __restrict__ z_last) {
    __shared__ unsigned int bitmap[D_SAE / 32];
    __shared__ __align__(16) unsigned long long cand[128];
    __shared__ int tmpIdx[KTOP];
    __shared__ float tmpVal[KTOP];
    __shared__ int warpCnt[4];

    const int b = blockIdx.x, tid = threadIdx.x, lane = tid & 31, w = tid >> 5;
    const int row0 = b * T_LEN;

    for (int i = tid; i < D_SAE; i += 128) z_last[(size_t)b * D_SAE + i] = 0.0f;
    for (int i = tid; i < D_SAE / 32; i += 128) bitmap[i] = 0;

    int   pIdx = 0;
    float pVal = 0.0f;
    int nprev = 0;

    int   nIdx = g_topidx[(size_t)row0 * 128 + tid];
    float nVal = g_topval[(size_t)row0 * 128 + tid];
    __syncthreads();

    for (int t = 0; t < T_LEN; ++t) {
        const int row = row0 + t;

        float preV = 0.0f, gV = 0.0f;
        if (tid < nprev) {
            preV = g_pre[(size_t)row * D_SAE + pIdx];
            gV   = g_gate[pIdx];
        }
        int nIdx2 = 0; float nVal2 = 0.0f;
        if (t + 1 < T_LEN) {
            nIdx2 = g_topidx[(size_t)(row + 1) * 128 + tid];
            nVal2 = g_topval[(size_t)(row + 1) * 128 + tid];
        }

        const int flag = !((bitmap[nIdx >> 5] >> (nIdx & 31)) & 1u);
        const unsigned bal = __ballot_sync(0xFFFFFFFFu, flag);
        if (lane == 0) warpCnt[w] = __popc(bal);
        __syncthreads();   // S1

        int off = __popc(bal & ((1u << lane) - 1));
#pragma unroll
        for (int q = 0; q < 4; ++q) off += (q < w) ? warpCnt[q] : 0;
        const int tn = min(warpCnt[0] + warpCnt[1] + warpCnt[2] + warpCnt[3], KTOP);
        if (flag && off < KTOP) cand[64 + off] = makeComp(nVal, nIdx);
        if (tid >= tn && tid < 64) cand[64 + tid] = 0ull;
        if (tid < 64)
            cand[tid] = (tid < nprev) ? makeComp(gV * pVal + preV, pIdx) : 0ull;
        if (tid < nprev) atomicAnd(&bitmap[pIdx >> 5], ~(1u << (pIdx & 31)));
        __syncthreads();   // S2

        {
            const unsigned long long me = cand[tid];
            int r0 = 0, r1 = 0;
#pragma unroll
            for (int j = 0; j < 128; j += 16) {
                const ulonglong2 c0 = *(const ulonglong2*)&cand[j];
                const ulonglong2 c1 = *(const ulonglong2*)&cand[j + 2];
                const ulonglong2 c2 = *(const ulonglong2*)&cand[j + 4];
                const ulonglong2 c3 = *(const ulonglong2*)&cand[j + 6];
                const ulonglong2 c4 = *(const ulonglong2*)&cand[j + 8];
                const ulonglong2 c5 = *(const ulonglong2*)&cand[j + 10];
                const ulonglong2 c6 = *(const ulonglong2*)&cand[j + 12];
                const ulonglong2 c7 = *(const ulonglong2*)&cand[j + 14];
                r0 += (c0.x > me) + (c0.y > me) + (c1.x > me) + (c1.y > me)
                    + (c2.x > me) + (c2.y > me) + (c3.x > me) + (c3.y > me);
                r1 += (c4.x > me) + (c4.y > me) + (c5.x > me) + (c5.y > me)
                    + (c6.x > me) + (c6.y > me) + (c7.x > me) + (c7.y > me);
            }
            const int r = r0 + r1;
            if (me != 0ull && r < KTOP) {
                tmpIdx[r] = (int)(0xFFFFFFFFu - (unsigned int)me);
                tmpVal[r] = fmaxf(keyToFloat((unsigned int)(me >> 32)), 0.0f);
            }
        }
        __syncthreads();   // S3

        if (tid < KTOP) {
            pIdx = tmpIdx[tid];
            pVal = tmpVal[tid];
            atomicOr(&bitmap[pIdx >> 5], 1u << (pIdx & 31));
            g_zidx[row * KTOP + tid] = pIdx;
            g_zval[row * KTOP + tid] = pVal;
            if (t == T_LEN - 1) z_last[(size_t)b * D_SAE + pIdx] = pVal;
        }
        nprev = KTOP;
        nIdx = nIdx2; nVal = nVal2;
        __syncthreads();   // S4
    }
}

// ======================================================================
// Kernel D: sparse decode + per-row squared error + fused final loss.
// ======================================================================
__global__ __launch_bounds__(192) void decode_kernel(const float* __restrict__ X,
                                                     const float* __restrict__ Wd,
                                                     const float* __restrict__ b_dec,
                                                     float* __restrict__ xhat,
                                                     float* __restrict__ out_loss) {
    __shared__ int sIdx[KTOP];
    __shared__ float sVal[KTOP];
    __shared__ float red[192];
    __shared__ unsigned int sLast;
    const int row = blockIdx.x, tid = threadIdx.x;
    if (tid < KTOP) {
        sIdx[tid] = g_zidx[row * KTOP + tid];
        sVal[tid] = g_zval[row * KTOP + tid];
    }
    __syncthreads();

    float4 acc = *(const float4*)(b_dec + tid * 4);
#pragma unroll 4
    for (int k = 0; k < KTOP; ++k) {
        const float v = sVal[k];
        const float4 wv = *(const float4*)(Wd + (size_t)sIdx[k] * D_IN + tid * 4);
        acc.x += v * wv.x; acc.y += v * wv.y; acc.z += v * wv.z; acc.w += v * wv.w;
    }
    float* op = xhat + (size_t)row * D_IN + tid * 4;
    op[0] = acc.x; op[1] = acc.y; op[2] = acc.z; op[3] = acc.w;

    const float4 xv = *(const float4*)(X + (size_t)row * D_IN + tid * 4);
    const float dx = acc.x - xv.x, dy = acc.y - xv.y, dz = acc.z - xv.z, dw = acc.w - xv.w;
    red[tid] = dx * dx + dy * dy + dz * dz + dw * dw;
    __syncthreads();
    for (int s = 96; s >= 6; s >>= 1) {
        if (tid < s) red[tid] += red[tid + s];
        __syncthreads();
    }
    if (tid == 0) {
        float total = 0.f;
        for (int i = 0; i < 6; ++i) total += red[i];
        g_rowloss[row] = total;
        __threadfence();
        sLast = atomicAdd(&g_done, 1u);
    }
    __syncthreads();

    if (sLast == (unsigned int)(NROWS - 1)) {
        if (tid == 0) g_done = 0;   // reset for next graph replay
        float acc2 = 0.0f;
        for (int i = tid; i < NROWS; i += 192) acc2 += g_rowloss[i];
        red[tid] = acc2;
        __syncthreads();
        for (int s = 96; s >= 6; s >>= 1) {
            if (tid < s) red[tid] += red[tid + s];
            __syncthreads();
        }
        if (tid == 0) {
            float total = 0.f;
            for (int i = 0; i < 6; ++i) total += red[i];
            out_loss[0] = total / (float)NROWS;
        }
    }
}

// ======================================================================
extern "C" void kernel_launch(void* const* d_in, const int* in_sizes, int n_in,
                              void* d_out, int out_size) {
    const float* x        = (const float*)d_in[0];
    const float* W_enc    = (const float*)d_in[1];
    const float* W_dec    = (const float*)d_in[2];
    const float* b_enc    = (const float*)d_in[3];
    const float* b_dec    = (const float*)d_in[4];
    const float* gate_raw = (const float*)d_in[5];

    float* out       = (float*)d_out;
    float* out_loss  = out;
    float* out_xhat  = out + 1;
    float* out_zlast = out + 1 + (size_t)NROWS * D_IN;

    dim3 gGrid(D_SAE / 64, NROWS / 128);  // (192, 16) = 3072 CTAs, 2/SM
    gemm_enc<<<gGrid, 256>>>(x, W_enc, b_enc);
    topk128<<<NROWS, 256>>>(gate_raw);
    scan_kernel<<<BATCH, 128>>>(out_zlast);
    decode_kernel<<<NROWS, 192>>>(x, W_dec, b_dec, out_xhat, out_loss);
}